// round 17
// baseline (speedup 1.0000x reference)
#include <cuda_runtime.h>
#include <math.h>

#define NB  8
#define CC  64
#define HH  512
#define WW  257
#define BB  8
#define NN  (HH*WW)      // 131584
#define NG  (NN/4)       // 32896 float4 groups per batch
#define NG16 (NN/16)     // 8224 16-pixel units per batch (= 32*257)
#define RBT 64                            // k_reduce block threads
#define GX16 ((NG16 + RBT - 1) / RBT)     // 129 blocks in x
#define TOTAL_BLOCKS (GX16 * BB * 2)      // 2064 (x2 for low/high split)

// Device-global scratch (no cudaMalloc allowed). Zero at module load; the
// fused MLP phase snapshots then resets everything, so each graph replay
// starts from a clean state. g_bands4 is rewritten identically every call.
__device__ float        g_acc[BB][NB][4];  // [b][band][S1_low,S2_low,S1_high,S2_high]
__device__ float        g_cnt[NB];
__device__ float        g_alpha[BB*NB];
__device__ unsigned int g_ticket;
__device__ uchar4       g_bands4[NG];      // band ids per float4 group

#define XSHIFT 0.8f   // x = mean-over-channels log1p(|z|) is ~0.81 +- 0.05

__device__ __forceinline__ float f_sqrt_approx(float x){
    float r; asm("sqrt.approx.f32 %0, %1;" : "=f"(r) : "f"(x)); return r;
}
__device__ __forceinline__ float f_lg2_approx(float x){
    float r; asm("lg2.approx.f32 %0, %1;" : "=f"(r) : "f"(x)); return r;
}

// Exact replication of the reference band assignment (bit-identical fp32 ops).
__device__ __forceinline__ int band_of(int n){
    int iy = n / WW;
    int ix = n - iy * WW;
    float fy = (float)(iy < 256 ? iy : iy - 512) * (1.0f/512.0f);
    float fx = (float)ix * (1.0f/512.0f);
    float r  = __fsqrt_rn(fx*fx + fy*fy);
    float rn = __fdiv_rn(r, 0.70710678118654752440f);
    int band = (rn > 0.125f) + (rn > 0.25f) + (rn > 0.375f) + (rn > 0.5f)
             + (rn > 0.625f) + (rn > 0.75f) + (rn > 0.875f);
    return band;
}

__device__ __forceinline__ float fixf(float x){
    if (isnan(x)) return 0.0f;
    if (isinf(x)) return x > 0.f ? 50.0f : -50.0f;
    return x;
}

// 4 magnitudes from one float4 pair into products P[o..o+3]
#define MAG4(P, O, R, I)                                            \
    P[(O)+0] *= 1.0f + f_sqrt_approx((R).x*(R).x + (I).x*(I).x);    \
    P[(O)+1] *= 1.0f + f_sqrt_approx((R).y*(R).y + (I).y*(I).y);    \
    P[(O)+2] *= 1.0f + f_sqrt_approx((R).z*(R).z + (I).z*(I).z);    \
    P[(O)+3] *= 1.0f + f_sqrt_approx((R).w*(R).w + (I).w*(I).w);

__global__ void __launch_bounds__(RBT)
k_reduce(const float* __restrict__ lre, const float* __restrict__ lim,
         const float* __restrict__ hre, const float* __restrict__ him,
         const float* __restrict__ W1,  const float* __restrict__ b1,
         const float* __restrict__ W2,  const float* __restrict__ b2,
         const float* __restrict__ bias){
    __shared__ float s_acc[NB][2];   // this block's (batch, half) accumulators
    __shared__ float s_cnt[NB];
    __shared__ bool  s_last;
    int t    = threadIdx.x;
    int lane = t & 31;
    if (t < NB*2) ((float*)s_acc)[t] = 0.0f;
    if (t < NB)   s_cnt[t] = 0.0f;
    __syncthreads();

    int b    = blockIdx.y;
    int half = blockIdx.z;           // 0 = low pair, 1 = high pair
    const float* re = half ? hre : lre;
    const float* im = half ? him : lim;

    int g16 = blockIdx.x * RBT + t;  // NG16 % 32 == 0 -> warp-uniform guard
    if (g16 < NG16) {
        int    n0   = g16 * 16;
        size_t base = ((size_t)b * CC) * (size_t)NN + (size_t)n0;

        float s[16];
        #pragma unroll
        for (int k = 0; k < 16; k++) s[k] = 0.f;

        // 8 groups of 8 channels; per group accumulate PRODUCT of (1+|z|) per
        // pixel slot, one lg2 per slot per group. 16 contiguous pixels per
        // thread on one (re,im) stream pair: each warp reads 2KB contiguous
        // per stream per channel.
        for (int grp = 0; grp < 8; grp++){
            float p[16];
            #pragma unroll
            for (int k = 0; k < 16; k++) p[k] = 1.f;
            size_t off = base + (size_t)(grp * 8) * NN;
            #pragma unroll
            for (int cc = 0; cc < 8; cc++){
                const float4* pr = (const float4*)(re + off);
                const float4* pi = (const float4*)(im + off);
                float4 r0 = __ldcs(pr),     i0 = __ldcs(pi);
                float4 r1 = __ldcs(pr + 1), i1 = __ldcs(pi + 1);
                float4 r2 = __ldcs(pr + 2), i2 = __ldcs(pi + 2);
                float4 r3 = __ldcs(pr + 3), i3 = __ldcs(pi + 3);
                off += NN;
                MAG4(p, 0,  r0, i0)
                MAG4(p, 4,  r1, i1)
                MAG4(p, 8,  r2, i2)
                MAG4(p, 12, r3, i3)
            }
            #pragma unroll
            for (int k = 0; k < 16; k++) s[k] += f_lg2_approx(p[k]);
        }

        const float sc = 0.69314718055994530942f / 64.0f;  // ln2 / C
        float d[16];
        #pragma unroll
        for (int k = 0; k < 16; k++) d[k] = s[k]*sc - XSHIFT;

        int bd[16];
        #pragma unroll
        for (int k = 0; k < 16; k++) bd[k] = band_of(n0 + k);

        // side effect: persist band table for k_write (one writer set only)
        if (b == 0 && half == 0){
            #pragma unroll
            for (int q = 0; q < 4; q++){
                g_bands4[g16*4 + q] = make_uchar4(
                    (unsigned char)bd[q*4+0], (unsigned char)bd[q*4+1],
                    (unsigned char)bd[q*4+2], (unsigned char)bd[q*4+3]);
            }
        }

        bool merged = true;
        #pragma unroll
        for (int k = 1; k < 16; k++) merged &= (bd[k] == bd[0]);

        float S1 = 0.f, S2 = 0.f;
        #pragma unroll
        for (int k = 0; k < 16; k++){ S1 += d[k]; S2 += d[k]*d[k]; }

        const unsigned m = 0xffffffffu;
        int  bref = __shfl_sync(m, bd[0], 0);
        bool uni  = __all_sync(m, merged && (bd[0] == bref));

        if (uni){
            // whole warp (512 contiguous pixels) in one band: 2 atomics/warp
            #pragma unroll
            for (int o = 16; o > 0; o >>= 1){
                S1 += __shfl_xor_sync(m, S1, o);
                S2 += __shfl_xor_sync(m, S2, o);
            }
            if (lane == 0){
                atomicAdd(&s_acc[bref][0], S1);
                atomicAdd(&s_acc[bref][1], S2);
                if (b == 0 && half == 0) atomicAdd(&s_cnt[bref], 512.0f);
            }
        } else if (merged){
            atomicAdd(&s_acc[bd[0]][0], S1);
            atomicAdd(&s_acc[bd[0]][1], S2);
            if (b == 0 && half == 0) atomicAdd(&s_cnt[bd[0]], 16.0f);
        } else {
            #pragma unroll
            for (int k = 0; k < 16; k++){
                atomicAdd(&s_acc[bd[k]][0], d[k]);
                atomicAdd(&s_acc[bd[k]][1], d[k]*d[k]);
                if (b == 0 && half == 0) atomicAdd(&s_cnt[bd[k]], 1.0f);
            }
        }
    }
    __syncthreads();

    // block -> global: slot [half*2 + q] (NB*2 = 16 <= 64 threads)
    if (t < NB*2){
        int bd_ = t >> 1, q = t & 1;
        float v = s_acc[bd_][q];
        if (v != 0.0f) atomicAdd(&g_acc[b][bd_][half*2 + q], v);
    }
    if (t < NB && b == 0 && half == 0){
        float v = s_cnt[t];
        if (v != 0.0f) atomicAdd(&g_cnt[t], v);
    }

    // last-block ticket: the final block runs the tiny MLP and resets state
    __threadfence();
    __syncthreads();
    if (t == 0){
        unsigned v = atomicAdd(&g_ticket, 1u);
        s_last = (v == (unsigned)(TOTAL_BLOCKS - 1));
    }
    __syncthreads();
    if (!s_last) return;

    __threadfence();  // acquire: make all blocks' atomics visible

    // Phase A: SNAPSHOT accumulators into registers (BB*NB = 64 == RBT).
    double cnt = 0.0, s1l = 0.0, s2l = 0.0, s1h = 0.0, s2h = 0.0;
    {
        int bb = t >> 3, j = t & 7;
        cnt = (double)__ldcg(&g_cnt[j]);
        s1l = (double)__ldcg(&g_acc[bb][j][0]);
        s2l = (double)__ldcg(&g_acc[bb][j][1]);
        s1h = (double)__ldcg(&g_acc[bb][j][2]);
        s2h = (double)__ldcg(&g_acc[bb][j][3]);
    }

    // Phase B: barrier so no reset can precede any snapshot read.
    __syncthreads();

    // Phase C: reset scratch for the next graph replay (256 entries, 64 thr).
    for (int i = t; i < BB*NB*4; i += RBT) ((float*)g_acc)[i] = 0.0f;
    if (t < NB) g_cnt[t] = 0.0f;
    if (t == 0) g_ticket = 0u;

    // Phase D: MLP from registers only.
    {
        int j = t & 7;
        double c1  = cnt < 1.0 ? 1.0 : cnt;
        double dml = s1l / c1, dmh = s1h / c1;
        double ml  = (double)XSHIFT + dml;
        double mh  = (double)XSHIFT + dmh;
        double vl  = s2l / c1 - dml*dml; if (vl < 0.0) vl = 0.0;
        double vh  = s2h / c1 - dmh*dmh; if (vh < 0.0) vh = 0.0;

        float fe0 = fixf((float)ml);
        float fe1 = fixf((float)mh);
        float fe2 = fixf((float)sqrt(vl));
        float fe3 = fixf((float)sqrt(vh));

        float acc = b2[0] + bias[j];
        #pragma unroll
        for (int i = 0; i < 32; i++){
            float a = b1[i];
            a += fe0*W1[i*4+0];
            a += fe1*W1[i*4+1];
            a += fe2*W1[i*4+2];
            a += fe3*W1[i*4+3];
            float gl = 0.5f * a * (1.0f + erff(a * 0.70710678118654752440f));
            acc += gl * W2[i];
        }
        g_alpha[t] = 1.0f / (1.0f + expf(-acc));
    }
}

// table-driven alpha broadcast: R10's measured-fastest config (4.7-5.0us)
__global__ void __launch_bounds__(256)
k_write(float* __restrict__ out){
    __shared__ float s_alpha[NB];
    int b = blockIdx.y;
    if (threadIdx.x < NB) s_alpha[threadIdx.x] = g_alpha[b * NB + threadIdx.x];
    __syncthreads();

    int g = blockIdx.x * blockDim.x + threadIdx.x;
    if (g >= NG) return;
    uchar4 tb = g_bands4[g];
    float4 v;
    v.x = s_alpha[tb.x];
    v.y = s_alpha[tb.y];
    v.z = s_alpha[tb.z];
    v.w = s_alpha[tb.w];
    ((float4*)(out + (size_t)b * NN))[g] = v;
}

extern "C" void kernel_launch(void* const* d_in, const int* in_sizes, int n_in,
                              void* d_out, int out_size){
    const float* lre  = (const float*)d_in[0];
    const float* lim  = (const float*)d_in[1];
    const float* hre  = (const float*)d_in[2];
    const float* him  = (const float*)d_in[3];
    const float* W1   = (const float*)d_in[4];
    const float* b1   = (const float*)d_in[5];
    const float* W2   = (const float*)d_in[6];
    const float* b2   = (const float*)d_in[7];
    const float* bias = (const float*)d_in[8];
    float* out = (float*)d_out;

    dim3 rgrid(GX16, BB, 2);
    k_reduce<<<rgrid, RBT>>>(lre, lim, hre, him, W1, b1, W2, b2, bias);
    dim3 wgrid((NG + 255) / 256, BB);
    k_write<<<wgrid, 256>>>(out);
}